// round 13
// baseline (speedup 1.0000x reference)
#include <cuda_runtime.h>
#include <cuda_bf16.h>
#include <mma.h>

using namespace nvcuda;

#define B_  2
#define H_  8
#define LQ  256
#define LK  512
#define DM  512
#define DK  64

#define AS_STRIDE 48
#define BS_STRIDE 80

// Scratch (device globals — no allocations allowed)
__device__ float g_Q[B_*LQ*DM];
__device__ float g_K[B_*LK*DM];
__device__ float g_V[B_*LK*DM];
__device__ float g_X[B_*LQ*DM];
__device__ int   g_idx[B_*LK];
__device__ int   g_cnt[B_];
__device__ float g_mult[B_];

__device__ __forceinline__ float fast_tanh(float x) {
    float r; asm("tanh.approx.f32 %0, %1;" : "=f"(r) : "f"(x)); return r;
}

// ---------------------------------------------------------------------------
// Deterministic mask compaction, 256 threads per batch: pair-load + scan.
// ---------------------------------------------------------------------------
__device__ void compact_body(const int* __restrict__ mask, int b) {
    __shared__ int s[256];
    int t = threadIdx.x;
    int m0 = (mask[b*LK + 2*t]     != 0) ? 1 : 0;
    int m1 = (mask[b*LK + 2*t + 1] != 0) ? 1 : 0;
    int ps = m0 + m1;
    s[t] = ps;
    __syncthreads();
    for (int off = 1; off < 256; off <<= 1) {
        int v = (t >= off) ? s[t - off] : 0;
        __syncthreads();
        if (t >= off) s[t] += v;
        __syncthreads();
    }
    int incl  = s[t];
    int total = s[255];
    int r0 = incl - ps + m0;
    int r1 = incl;
    if (m0) g_idx[b*LK + r0 - 1] = 2*t;
    if (m1) g_idx[b*LK + r1 - 1] = 2*t + 1;
    if (total == 0) {            // all-masked: uniform softmax fallback
        g_idx[b*LK + 2*t]     = 2*t;
        g_idx[b*LK + 2*t + 1] = 2*t + 1;
    }
    if (t == 0) {
        g_cnt[b]  = (total == 0) ? LK : total;
        g_mult[b] = (total == 0) ? 0.f : 1.f;
    }
}

// ---------------------------------------------------------------------------
// bf16x3-split tensor-core GEMM, 64x64 tile, DOUBLE-BUFFERED (1 sync/iter).
// acc += hi*hi + hi*lo + lo*hi (lo*lo dropped; verified rel_err 6.6e-6).
// ---------------------------------------------------------------------------
__device__ __forceinline__ void gemm_body64(const float* __restrict__ A,
                                            const float* __restrict__ Bw,
                                            float* __restrict__ C,
                                            int m0, int n0, int kbeg, int nk)
{
    __shared__ __align__(32) __nv_bfloat16 As_hi[2][64][AS_STRIDE];
    __shared__ __align__(32) __nv_bfloat16 As_lo[2][64][AS_STRIDE];
    __shared__ __align__(32) __nv_bfloat16 Bs_hi[2][16][BS_STRIDE];
    __shared__ __align__(32) __nv_bfloat16 Bs_lo[2][16][BS_STRIDE];

    int t = threadIdx.x;
    int warp = t >> 5;
    int arow = t >> 2,  akc = (t & 3) * 4;
    int bkr  = t >> 4,  bnc = (t & 15) * 4;

    const float* Ap = A  + (m0 + arow) * DM + kbeg + akc;
    const float* Bp = Bw + (kbeg + bkr) * DM + n0 + bnc;

    int wr = warp >> 1;
    int wc = (warp & 1) * 32;

    wmma::fragment<wmma::accumulator, 16,16,16, float> acc0, acc1;
    wmma::fill_fragment(acc0, 0.f);
    wmma::fill_fragment(acc1, 0.f);

    float4 pa = *(const float4*)Ap;
    float4 pb = *(const float4*)Bp;

    // prologue: fill buffer 0
    {
        float va[4] = {pa.x, pa.y, pa.z, pa.w};
        #pragma unroll
        for (int u = 0; u < 4; u++) {
            __nv_bfloat16 hh = __float2bfloat16(va[u]);
            As_hi[0][arow][akc+u] = hh;
            As_lo[0][arow][akc+u] = __float2bfloat16(va[u] - __bfloat162float(hh));
        }
        float vb[4] = {pb.x, pb.y, pb.z, pb.w};
        #pragma unroll
        for (int u = 0; u < 4; u++) {
            __nv_bfloat16 hh = __float2bfloat16(vb[u]);
            Bs_hi[0][bkr][bnc+u] = hh;
            Bs_lo[0][bkr][bnc+u] = __float2bfloat16(vb[u] - __bfloat162float(hh));
        }
    }
    __syncthreads();

    int cur = 0;
    for (int kt = 0; kt < nk; kt++) {
        bool more = (kt + 1 < nk);
        if (more) {
            pa = *(const float4*)(Ap + (kt + 1) * 16);
            pb = *(const float4*)(Bp + (kt + 1) * 16 * DM);
        }
        wmma::fragment<wmma::matrix_a, 16,16,16, __nv_bfloat16, wmma::row_major> a_hi, a_lo;
        wmma::fragment<wmma::matrix_b, 16,16,16, __nv_bfloat16, wmma::row_major> b_hi, b_lo;
        wmma::load_matrix_sync(a_hi, &As_hi[cur][wr*16][0], AS_STRIDE);
        wmma::load_matrix_sync(a_lo, &As_lo[cur][wr*16][0], AS_STRIDE);

        wmma::load_matrix_sync(b_hi, &Bs_hi[cur][0][wc], BS_STRIDE);
        wmma::load_matrix_sync(b_lo, &Bs_lo[cur][0][wc], BS_STRIDE);
        wmma::mma_sync(acc0, a_hi, b_hi, acc0);
        wmma::mma_sync(acc0, a_hi, b_lo, acc0);
        wmma::mma_sync(acc0, a_lo, b_hi, acc0);

        wmma::load_matrix_sync(b_hi, &Bs_hi[cur][0][wc+16], BS_STRIDE);
        wmma::load_matrix_sync(b_lo, &Bs_lo[cur][0][wc+16], BS_STRIDE);
        wmma::mma_sync(acc1, a_hi, b_hi, acc1);
        wmma::mma_sync(acc1, a_hi, b_lo, acc1);
        wmma::mma_sync(acc1, a_lo, b_hi, acc1);

        if (more) {                     // fill the other buffer (no alias with cur)
            int nxt = cur ^ 1;
            float va[4] = {pa.x, pa.y, pa.z, pa.w};
            #pragma unroll
            for (int u = 0; u < 4; u++) {
                __nv_bfloat16 hh = __float2bfloat16(va[u]);
                As_hi[nxt][arow][akc+u] = hh;
                As_lo[nxt][arow][akc+u] = __float2bfloat16(va[u] - __bfloat162float(hh));
            }
            float vb[4] = {pb.x, pb.y, pb.z, pb.w};
            #pragma unroll
            for (int u = 0; u < 4; u++) {
                __nv_bfloat16 hh = __float2bfloat16(vb[u]);
                Bs_hi[nxt][bkr][bnc+u] = hh;
                Bs_lo[nxt][bkr][bnc+u] = __float2bfloat16(vb[u] - __bfloat162float(hh));
            }
        }
        __syncthreads();
        cur ^= 1;
    }
    wmma::store_matrix_sync(&C[(m0 + wr*16) * DM + n0 + wc],      acc0, DM, wmma::mem_row_major);
    wmma::store_matrix_sync(&C[(m0 + wr*16) * DM + n0 + wc + 16], acc1, DM, wmma::mem_row_major);
}

// ---------------------------------------------------------------------------
// 32x64-tile variant (one 16x16 tile per warp), double-buffered. Used by
// out_gemm with grid (8,16) = 128 CTAs -> NO split-K, NO reduce kernel.
// ---------------------------------------------------------------------------
__device__ __forceinline__ void gemm_body32(const float* __restrict__ A,
                                            const float* __restrict__ Bw,
                                            float* __restrict__ C,
                                            int m0, int n0, int nk)
{
    __shared__ __align__(32) __nv_bfloat16 As_hi[2][32][AS_STRIDE];
    __shared__ __align__(32) __nv_bfloat16 As_lo[2][32][AS_STRIDE];
    __shared__ __align__(32) __nv_bfloat16 Bs_hi[2][16][BS_STRIDE];
    __shared__ __align__(32) __nv_bfloat16 Bs_lo[2][16][BS_STRIDE];

    int t = threadIdx.x;
    int warp = t >> 5;
    bool aldr = (t < 128);
    int arow = t >> 2,  akc = (t & 3) * 4;     // valid for t<128: rows 0..31
    int bkr  = t >> 4,  bnc = (t & 15) * 4;

    const float* Ap = A  + (m0 + arow) * DM + akc;
    const float* Bp = Bw + bkr * DM + n0 + bnc;

    int wr = warp >> 2;            // 0..1
    int wc = (warp & 3) * 16;      // 0,16,32,48

    wmma::fragment<wmma::accumulator, 16,16,16, float> acc0;
    wmma::fill_fragment(acc0, 0.f);

    float4 pa, pb;
    if (aldr) pa = *(const float4*)Ap;
    pb = *(const float4*)Bp;

    {
        if (aldr) {
            float va[4] = {pa.x, pa.y, pa.z, pa.w};
            #pragma unroll
            for (int u = 0; u < 4; u++) {
                __nv_bfloat16 hh = __float2bfloat16(va[u]);
                As_hi[0][arow][akc+u] = hh;
                As_lo[0][arow][akc+u] = __float2bfloat16(va[u] - __bfloat162float(hh));
            }
        }
        float vb[4] = {pb.x, pb.y, pb.z, pb.w};
        #pragma unroll
        for (int u = 0; u < 4; u++) {
            __nv_bfloat16 hh = __float2bfloat16(vb[u]);
            Bs_hi[0][bkr][bnc+u] = hh;
            Bs_lo[0][bkr][bnc+u] = __float2bfloat16(vb[u] - __bfloat162float(hh));
        }
    }
    __syncthreads();

    int cur = 0;
    for (int kt = 0; kt < nk; kt++) {
        bool more = (kt + 1 < nk);
        if (more) {
            if (aldr) pa = *(const float4*)(Ap + (kt + 1) * 16);
            pb = *(const float4*)(Bp + (kt + 1) * 16 * DM);
        }
        wmma::fragment<wmma::matrix_a, 16,16,16, __nv_bfloat16, wmma::row_major> a_hi, a_lo;
        wmma::fragment<wmma::matrix_b, 16,16,16, __nv_bfloat16, wmma::row_major> b_hi, b_lo;
        wmma::load_matrix_sync(a_hi, &As_hi[cur][wr*16][0], AS_STRIDE);
        wmma::load_matrix_sync(a_lo, &As_lo[cur][wr*16][0], AS_STRIDE);
        wmma::load_matrix_sync(b_hi, &Bs_hi[cur][0][wc], BS_STRIDE);
        wmma::load_matrix_sync(b_lo, &Bs_lo[cur][0][wc], BS_STRIDE);
        wmma::mma_sync(acc0, a_hi, b_hi, acc0);
        wmma::mma_sync(acc0, a_hi, b_lo, acc0);
        wmma::mma_sync(acc0, a_lo, b_hi, acc0);

        if (more) {
            int nxt = cur ^ 1;
            if (aldr) {
                float va[4] = {pa.x, pa.y, pa.z, pa.w};
                #pragma unroll
                for (int u = 0; u < 4; u++) {
                    __nv_bfloat16 hh = __float2bfloat16(va[u]);
                    As_hi[nxt][arow][akc+u] = hh;
                    As_lo[nxt][arow][akc+u] = __float2bfloat16(va[u] - __bfloat162float(hh));
                }
            }
            float vb[4] = {pb.x, pb.y, pb.z, pb.w};
            #pragma unroll
            for (int u = 0; u < 4; u++) {
                __nv_bfloat16 hh = __float2bfloat16(vb[u]);
                Bs_hi[nxt][bkr][bnc+u] = hh;
                Bs_lo[nxt][bkr][bnc+u] = __float2bfloat16(vb[u] - __bfloat162float(hh));
            }
        }
        __syncthreads();
        cur ^= 1;
    }
    wmma::store_matrix_sync(&C[(m0 + wr*16) * DM + n0 + wc], acc0, DM, wmma::mem_row_major);
}

// ---------------------------------------------------------------------------
__global__ void __launch_bounds__(256) proj_kernel(const float* __restrict__ query,
                                                   const float* __restrict__ key_,
                                                   const float* __restrict__ value,
                                                   const float* __restrict__ Wq,
                                                   const float* __restrict__ Wk,
                                                   const float* __restrict__ Wv,
                                                   const int* __restrict__ mask)
{
    int z = blockIdx.z;
    const float* A; const float* W; float* C; int mrows;
    if (z == 0)      { A = query; W = Wq; C = g_Q; mrows = B_*LQ; }
    else if (z == 1) { A = key_;  W = Wk; C = g_K; mrows = B_*LK; }
    else             { A = value; W = Wv; C = g_V; mrows = B_*LK; }
    int m0 = blockIdx.y * 64;
    if (m0 >= mrows) {
        if (z == 0 && blockIdx.y == 8 && blockIdx.x < 2)
            compact_body(mask, blockIdx.x);
        return;
    }
    gemm_body64(A, W, C, m0, blockIdx.x * 64, 0, DM/16);
}

// out = X @ Wo. 32x64 tiles, grid (8,16) = 128 CTAs, full K per CTA.
__global__ void __launch_bounds__(256) out_gemm(const float* __restrict__ Wo,
                                                float* __restrict__ out)
{
    gemm_body32(g_X, Wo, out, blockIdx.y * 32, blockIdx.x * 64, DM/16);
}

// ---------------------------------------------------------------------------
// Fused additive attention, software-pipelined phases (verified R12).
// ---------------------------------------------------------------------------
__global__ void __launch_bounds__(256, 2) attn_kernel(const float* __restrict__ wa)
{
    __shared__ __align__(16) float qs[16][68];
    __shared__ __align__(16) float ks[32][68];
    __shared__ __align__(16) float vs[2][32][68];
    __shared__ float es[2][16][33];
    __shared__ __align__(16) float was[64];

    int blk = blockIdx.x;
    int ib = blk & 15, h = (blk >> 4) & 7, b = blk >> 7;
    int t = threadIdx.x, lane = t & 31, w = t >> 5;

    if (t < 64) was[t] = wa[t];

    const float* Qb = g_Q + (b*LQ + ib*16) * DM + h*DK;
    {
        int row = t >> 4, c4 = (t & 15) * 4;
        *(float4*)&qs[row][c4] = *(const float4*)&Qb[row*DM + c4];
    }

    int cnt    = g_cnt[b];
    float mult = g_mult[b];
    int nchunk = (cnt + 31) >> 5;

    float4 acc = make_float4(0,0,0,0);
    float denom = 0.f;
    int i2 = t >> 4, g = t & 15;

    const float* Kbase = g_K + b*LK*DM + h*DK;
    const float* Vbase = g_V + b*LK*DM + h*DK;
    const int*   idxb  = g_idx + b*LK;

    int ld_row = t >> 4, ld_c4 = (t & 15) * 4;
    float4 pk[2], pv[2];
    #pragma unroll
    for (int u = 0; u < 2; u++) {
        int row = ld_row + u*16;
        int src = (row < cnt) ? idxb[row] : 0;
        pk[u] = *(const float4*)&Kbase[src*DM + ld_c4];
        pv[u] = *(const float4*)&Vbase[src*DM + ld_c4];
    }

    for (int c = 0; c < nchunk; c++) {
        int buf = c & 1;
        #pragma unroll
        for (int u = 0; u < 2; u++) {
            int row = ld_row + u*16;
            *(float4*)&ks[row][ld_c4]      = pk[u];
            *(float4*)&vs[buf][row][ld_c4] = pv[u];
        }
        __syncthreads();
        if (c + 1 < nchunk) {
            #pragma unroll
            for (int u = 0; u < 2; u++) {
                int jj = (c + 1)*32 + ld_row + u*16;
                int src = (jj < cnt) ? idxb[jj] : 0;
                pk[u] = *(const float4*)&Kbase[src*DM + ld_c4];
                pv[u] = *(const float4*)&Vbase[src*DM + ld_c4];
            }
        }
        bool valid = (c*32 + lane) < cnt;
        #pragma unroll
        for (int ii = 0; ii < 2; ii++) {
            int i = w*2 + ii;
            float s0 = 0.f, s1 = 0.f, s2 = 0.f, s3 = 0.f;
            #pragma unroll
            for (int d4 = 0; d4 < 16; d4++) {
                float4 q4 = *(const float4*)&qs[i][d4*4];
                float4 k4 = *(const float4*)&ks[lane][d4*4];
                float4 w4 = *(const float4*)&was[d4*4];
                s0 += fast_tanh(q4.x + k4.x) * w4.x;
                s1 += fast_tanh(q4.y + k4.y) * w4.y;
                s2 += fast_tanh(q4.z + k4.z) * w4.z;
                s3 += fast_tanh(q4.w + k4.w) * w4.w;
            }
            float s = (s0 + s1) + (s2 + s3);
            es[buf][i][lane] = valid ? __expf(s * mult) : 0.f;
        }
        if (c > 0) {
            int pbuf = buf ^ 1;
            #pragma unroll
            for (int j = 0; j < 32; j++) {
                float e = es[pbuf][i2][j];
                float4 v = *(const float4*)&vs[pbuf][j][g*4];
                acc.x += e*v.x; acc.y += e*v.y; acc.z += e*v.z; acc.w += e*v.w;
                denom += e;
            }
        }
        __syncthreads();
    }
    {
        int pbuf = (nchunk - 1) & 1;
        #pragma unroll
        for (int j = 0; j < 32; j++) {
            float e = es[pbuf][i2][j];
            float4 v = *(const float4*)&vs[pbuf][j][g*4];
            acc.x += e*v.x; acc.y += e*v.y; acc.z += e*v.z; acc.w += e*v.w;
            denom += e;
        }
    }

    float inv = 1.f / denom;
    float* Xb = g_X + (b*LQ + ib*16 + i2) * DM + h*DK;
    *(float4*)&Xb[g*4] = make_float4(acc.x*inv, acc.y*inv, acc.z*inv, acc.w*inv);
}

// ---------------------------------------------------------------------------
extern "C" void kernel_launch(void* const* d_in, const int* in_sizes, int n_in,
                              void* d_out, int out_size)
{
    const float* query = (const float*)d_in[0];
    const float* key_  = (const float*)d_in[1];
    const float* value = (const float*)d_in[2];
    const int*   mask  = (const int*)  d_in[3];
    const float* Wq    = (const float*)d_in[4];
    const float* Wk    = (const float*)d_in[5];
    const float* Wv    = (const float*)d_in[6];
    const float* Wo    = (const float*)d_in[7];
    const float* wa    = (const float*)d_in[8];
    float* out = (float*)d_out;

    proj_kernel<<<dim3(8, 16, 3), 256>>>(query, key_, value, Wq, Wk, Wv, mask);
    attn_kernel<<<256, 256>>>(wa);
    out_gemm<<<dim3(8, 16), 256>>>(Wo, out);
}

// round 14
// speedup vs baseline: 1.0202x; 1.0202x over previous
#include <cuda_runtime.h>
#include <cuda_bf16.h>
#include <mma.h>

using namespace nvcuda;

#define B_  2
#define H_  8
#define LQ  256
#define LK  512
#define DM  512
#define DK  64

#define A_STRIDE 24   // 48B rows: ldmatrix bank shift 12 -> conflict-free, 16B aligned
#define B_STRIDE 72   // 144B rows: shift 4 -> conflict-free, 16B aligned

#define A_ROWS   (B_*LQ + 2*B_*LK)   // 2560: query(512) | key(1024) | value(1024)
#define W_ELEMS  (DM*DM)             // 262144 per weight

// Scratch (device globals — no allocations allowed)
__device__ float g_Q[B_*LQ*DM];
__device__ float g_K[B_*LK*DM];
__device__ float g_V[B_*LK*DM];
__device__ __nv_bfloat16 g_Ahi[A_ROWS*DM], g_Alo[A_ROWS*DM];
__device__ __nv_bfloat16 g_Whi[4*W_ELEMS], g_Wlo[4*W_ELEMS];   // Wq,Wk,Wv,Wo
__device__ __nv_bfloat16 g_Xhi[B_*LQ*DM], g_Xlo[B_*LQ*DM];
__device__ int   g_idx[B_*LK];
__device__ int   g_cnt[B_];
__device__ float g_mult[B_];

__device__ __forceinline__ float fast_tanh(float x) {
    float r; asm("tanh.approx.f32 %0, %1;" : "=f"(r) : "f"(x)); return r;
}

// ---------------------------------------------------------------------------
// One-shot hi/lo bf16 split of inputs and weights. Bandwidth-bound.
// float4 index space: [0, 327680) = A rows (q|k|v), then [.., 589824) = weights.
// ---------------------------------------------------------------------------
__global__ void __launch_bounds__(256) convert_kernel(
    const float* __restrict__ q, const float* __restrict__ k,
    const float* __restrict__ v,
    const float* __restrict__ wq, const float* __restrict__ wk,
    const float* __restrict__ wv, const float* __restrict__ wo)
{
    int i = blockIdx.x * 256 + threadIdx.x;   // float4 index
    int e = i * 4;
    const float* src; int off;
    __nv_bfloat16 *dh, *dl; int doff;
    if (i < (A_ROWS*DM)/4) {
        int row = e >> 9, col = e & 511;
        if (row < 512)       { src = q; off = row*DM + col; }
        else if (row < 1536) { src = k; off = (row-512)*DM + col; }
        else                 { src = v; off = (row-1536)*DM + col; }
        dh = g_Ahi; dl = g_Alo; doff = e;
    } else {
        int j = e - A_ROWS*DM;
        int widx = j >> 18, o2 = j & (W_ELEMS-1);
        src = (widx == 0) ? wq : (widx == 1) ? wk : (widx == 2) ? wv : wo;
        off = o2;
        dh = g_Whi; dl = g_Wlo; doff = j;
    }
    float4 vv = *(const float4*)&src[off];
    float a[4] = {vv.x, vv.y, vv.z, vv.w};
    __nv_bfloat16 h[4], l[4];
    #pragma unroll
    for (int u = 0; u < 4; u++) {
        h[u] = __float2bfloat16(a[u]);
        l[u] = __float2bfloat16(a[u] - __bfloat162float(h[u]));
    }
    ((__nv_bfloat162*)(dh + doff))[0] = __nv_bfloat162{h[0], h[1]};
    ((__nv_bfloat162*)(dh + doff))[1] = __nv_bfloat162{h[2], h[3]};
    ((__nv_bfloat162*)(dl + doff))[0] = __nv_bfloat162{l[0], l[1]};
    ((__nv_bfloat162*)(dl + doff))[1] = __nv_bfloat162{l[2], l[3]};
}

// ---------------------------------------------------------------------------
// Deterministic mask compaction, 256 threads per batch: pair-load + scan.
// ---------------------------------------------------------------------------
__device__ void compact_body(const int* __restrict__ mask, int b) {
    __shared__ int s[256];
    int t = threadIdx.x;
    int m0 = (mask[b*LK + 2*t]     != 0) ? 1 : 0;
    int m1 = (mask[b*LK + 2*t + 1] != 0) ? 1 : 0;
    int ps = m0 + m1;
    s[t] = ps;
    __syncthreads();
    for (int off = 1; off < 256; off <<= 1) {
        int vv = (t >= off) ? s[t - off] : 0;
        __syncthreads();
        if (t >= off) s[t] += vv;
        __syncthreads();
    }
    int incl  = s[t];
    int total = s[255];
    int r0 = incl - ps + m0;
    int r1 = incl;
    if (m0) g_idx[b*LK + r0 - 1] = 2*t;
    if (m1) g_idx[b*LK + r1 - 1] = 2*t + 1;
    if (total == 0) {
        g_idx[b*LK + 2*t]     = 2*t;
        g_idx[b*LK + 2*t + 1] = 2*t + 1;
    }
    if (t == 0) {
        g_cnt[b]  = (total == 0) ? LK : total;
        g_mult[b] = (total == 0) ? 0.f : 1.f;
    }
}

// ---------------------------------------------------------------------------
// 64x64 bf16x3 GEMM body, pre-split operands. Per K-step per thread:
// 2x LDG.128 + 2x STS.128 (no conversion). 6 fragment loads + 6 mma per warp.
// ---------------------------------------------------------------------------
__device__ __forceinline__ void gemm64(int abase, int m0, int wbase, int n0,
                                       float* __restrict__ C)
{
    __shared__ __align__(16) __nv_bfloat16 sAh[64][A_STRIDE], sAl[64][A_STRIDE];
    __shared__ __align__(16) __nv_bfloat16 sBh[16][B_STRIDE], sBl[16][B_STRIDE];

    int t = threadIdx.x, warp = t >> 5;
    bool hi = (t < 128);
    int ar = (t & 127) >> 1, ac = (t & 1) * 8;     // A: 64 rows x 2 chunks of 8 bf16
    int br = (t & 127) >> 3, bc = (t & 7) * 8;     // B: 16 rows x 8 chunks

    const __nv_bfloat16* Asrc = (hi ? g_Ahi : g_Alo) + (abase + m0 + ar)*DM + ac;
    const __nv_bfloat16* Bsrc = (hi ? g_Whi : g_Wlo) + wbase + br*DM + n0 + bc;
    __nv_bfloat16 (*sA)[A_STRIDE] = hi ? sAh : sAl;
    __nv_bfloat16 (*sB)[B_STRIDE] = hi ? sBh : sBl;

    int wr = warp >> 1, wc = (warp & 1) * 32;

    wmma::fragment<wmma::accumulator, 16,16,16, float> acc0, acc1;
    wmma::fill_fragment(acc0, 0.f);
    wmma::fill_fragment(acc1, 0.f);

    uint4 pa = *(const uint4*)Asrc;
    uint4 pb = *(const uint4*)Bsrc;

    for (int kt = 0; kt < DM/16; kt++) {
        *(uint4*)&sA[ar][ac] = pa;
        *(uint4*)&sB[br][bc] = pb;
        __syncthreads();
        if (kt + 1 < DM/16) {
            pa = *(const uint4*)(Asrc + (kt + 1) * 16);
            pb = *(const uint4*)(Bsrc + (kt + 1) * 16 * DM);
        }
        wmma::fragment<wmma::matrix_a, 16,16,16, __nv_bfloat16, wmma::row_major> a_hi, a_lo;
        wmma::fragment<wmma::matrix_b, 16,16,16, __nv_bfloat16, wmma::row_major> b_hi, b_lo;
        wmma::load_matrix_sync(a_hi, &sAh[wr*16][0], A_STRIDE);
        wmma::load_matrix_sync(a_lo, &sAl[wr*16][0], A_STRIDE);

        wmma::load_matrix_sync(b_hi, &sBh[0][wc], B_STRIDE);
        wmma::load_matrix_sync(b_lo, &sBl[0][wc], B_STRIDE);
        wmma::mma_sync(acc0, a_hi, b_hi, acc0);
        wmma::mma_sync(acc0, a_hi, b_lo, acc0);
        wmma::mma_sync(acc0, a_lo, b_hi, acc0);

        wmma::load_matrix_sync(b_hi, &sBh[0][wc+16], B_STRIDE);
        wmma::load_matrix_sync(b_lo, &sBl[0][wc+16], B_STRIDE);
        wmma::mma_sync(acc1, a_hi, b_hi, acc1);
        wmma::mma_sync(acc1, a_hi, b_lo, acc1);
        wmma::mma_sync(acc1, a_lo, b_hi, acc1);
        __syncthreads();
    }
    wmma::store_matrix_sync(&C[(m0 + wr*16) * DM + n0 + wc],      acc0, DM, wmma::mem_row_major);
    wmma::store_matrix_sync(&C[(m0 + wr*16) * DM + n0 + wc + 16], acc1, DM, wmma::mem_row_major);
}

// ---------------------------------------------------------------------------
// Fused Q/K/V projections + mask compaction. Grid (8,16,3).
// ---------------------------------------------------------------------------
__global__ void __launch_bounds__(256) proj_kernel(const int* __restrict__ mask)
{
    int z = blockIdx.z;
    int abase, wbase, mrows; float* C;
    if (z == 0)      { abase = 0;    wbase = 0;         C = g_Q; mrows = B_*LQ; }
    else if (z == 1) { abase = 512;  wbase = W_ELEMS;   C = g_K; mrows = B_*LK; }
    else             { abase = 1536; wbase = 2*W_ELEMS; C = g_V; mrows = B_*LK; }
    int m0 = blockIdx.y * 64;
    if (m0 >= mrows) {
        if (z == 0 && blockIdx.y == 8 && blockIdx.x < 2)
            compact_body(mask, blockIdx.x);
        return;
    }
    gemm64(abase, m0, wbase, blockIdx.x * 64, C);
}

// ---------------------------------------------------------------------------
// out = X @ Wo. 32x64 tiles, grid (8,16) = 128 CTAs. X pre-split by attn.
// ---------------------------------------------------------------------------
__global__ void __launch_bounds__(256) out_gemm(float* __restrict__ out)
{
    __shared__ __align__(16) __nv_bfloat16 sAh[32][A_STRIDE], sAl[32][A_STRIDE];
    __shared__ __align__(16) __nv_bfloat16 sBh[16][B_STRIDE], sBl[16][B_STRIDE];

    int t = threadIdx.x, warp = t >> 5;
    int m0 = blockIdx.y * 32, n0 = blockIdx.x * 64;

    // A: 32 rows x 2 chunks x {hi,lo} = 128 slots -> threads t<128
    bool a_act = (t < 128);
    bool a_hi_half = (t < 64);
    int ar = (t & 63) >> 1, ac = (t & 1) * 8;
    // B: 16 rows x 8 chunks x {hi,lo} = 256 slots -> all threads
    bool b_hi_half = (t < 128);
    int br = (t & 127) >> 3, bc = (t & 7) * 8;

    const __nv_bfloat16* Asrc = (a_hi_half ? g_Xhi : g_Xlo) + (m0 + ar)*DM + ac;
    const __nv_bfloat16* Bsrc = (b_hi_half ? g_Whi : g_Wlo) + 3*W_ELEMS + br*DM + n0 + bc;
    __nv_bfloat16 (*sA)[A_STRIDE] = a_hi_half ? sAh : sAl;
    __nv_bfloat16 (*sB)[B_STRIDE] = b_hi_half ? sBh : sBl;

    int wr = warp >> 2, wc = (warp & 3) * 16;

    wmma::fragment<wmma::accumulator, 16,16,16, float> acc0;
    wmma::fill_fragment(acc0, 0.f);

    uint4 pa, pb;
    if (a_act) pa = *(const uint4*)Asrc;
    pb = *(const uint4*)Bsrc;

    for (int kt = 0; kt < DM/16; kt++) {
        if (a_act) *(uint4*)&sA[ar][ac] = pa;
        *(uint4*)&sB[br][bc] = pb;
        __syncthreads();
        if (kt + 1 < DM/16) {
            if (a_act) pa = *(const uint4*)(Asrc + (kt + 1) * 16);
            pb = *(const uint4*)(Bsrc + (kt + 1) * 16 * DM);
        }
        wmma::fragment<wmma::matrix_a, 16,16,16, __nv_bfloat16, wmma::row_major> a_h, a_l;
        wmma::fragment<wmma::matrix_b, 16,16,16, __nv_bfloat16, wmma::row_major> b_h, b_l;
        wmma::load_matrix_sync(a_h, &sAh[wr*16][0], A_STRIDE);
        wmma::load_matrix_sync(a_l, &sAl[wr*16][0], A_STRIDE);
        wmma::load_matrix_sync(b_h, &sBh[0][wc], B_STRIDE);
        wmma::load_matrix_sync(b_l, &sBl[0][wc], B_STRIDE);
        wmma::mma_sync(acc0, a_h, b_h, acc0);
        wmma::mma_sync(acc0, a_h, b_l, acc0);
        wmma::mma_sync(acc0, a_l, b_h, acc0);
        __syncthreads();
    }
    wmma::store_matrix_sync(&out[(m0 + wr*16) * DM + n0 + wc], acc0, DM, wmma::mem_row_major);
}

// ---------------------------------------------------------------------------
// Fused additive attention, software-pipelined phases (verified R12).
// Epilogue now writes the hi/lo bf16 split of X directly.
// ---------------------------------------------------------------------------
__global__ void __launch_bounds__(256, 2) attn_kernel(const float* __restrict__ wa)
{
    __shared__ __align__(16) float qs[16][68];
    __shared__ __align__(16) float ks[32][68];
    __shared__ __align__(16) float vs[2][32][68];
    __shared__ float es[2][16][33];
    __shared__ __align__(16) float was[64];

    int blk = blockIdx.x;
    int ib = blk & 15, h = (blk >> 4) & 7, b = blk >> 7;
    int t = threadIdx.x, lane = t & 31, w = t >> 5;

    if (t < 64) was[t] = wa[t];

    const float* Qb = g_Q + (b*LQ + ib*16) * DM + h*DK;
    {
        int row = t >> 4, c4 = (t & 15) * 4;
        *(float4*)&qs[row][c4] = *(const float4*)&Qb[row*DM + c4];
    }

    int cnt    = g_cnt[b];
    float mult = g_mult[b];
    int nchunk = (cnt + 31) >> 5;

    float4 acc = make_float4(0,0,0,0);
    float denom = 0.f;
    int i2 = t >> 4, g = t & 15;

    const float* Kbase = g_K + b*LK*DM + h*DK;
    const float* Vbase = g_V + b*LK*DM + h*DK;
    const int*   idxb  = g_idx + b*LK;

    int ld_row = t >> 4, ld_c4 = (t & 15) * 4;
    float4 pk[2], pv[2];
    #pragma unroll
    for (int u = 0; u < 2; u++) {
        int row = ld_row + u*16;
        int src = (row < cnt) ? idxb[row] : 0;
        pk[u] = *(const float4*)&Kbase[src*DM + ld_c4];
        pv[u] = *(const float4*)&Vbase[src*DM + ld_c4];
    }

    for (int c = 0; c < nchunk; c++) {
        int buf = c & 1;
        #pragma unroll
        for (int u = 0; u < 2; u++) {
            int row = ld_row + u*16;
            *(float4*)&ks[row][ld_c4]      = pk[u];
            *(float4*)&vs[buf][row][ld_c4] = pv[u];
        }
        __syncthreads();
        if (c + 1 < nchunk) {
            #pragma unroll
            for (int u = 0; u < 2; u++) {
                int jj = (c + 1)*32 + ld_row + u*16;
                int src = (jj < cnt) ? idxb[jj] : 0;
                pk[u] = *(const float4*)&Kbase[src*DM + ld_c4];
                pv[u] = *(const float4*)&Vbase[src*DM + ld_c4];
            }
        }
        bool valid = (c*32 + lane) < cnt;
        #pragma unroll
        for (int ii = 0; ii < 2; ii++) {
            int i = w*2 + ii;
            float s0 = 0.f, s1 = 0.f, s2 = 0.f, s3 = 0.f;
            #pragma unroll
            for (int d4 = 0; d4 < 16; d4++) {
                float4 q4 = *(const float4*)&qs[i][d4*4];
                float4 k4 = *(const float4*)&ks[lane][d4*4];
                float4 w4 = *(const float4*)&was[d4*4];
                s0 += fast_tanh(q4.x + k4.x) * w4.x;
                s1 += fast_tanh(q4.y + k4.y) * w4.y;
                s2 += fast_tanh(q4.z + k4.z) * w4.z;
                s3 += fast_tanh(q4.w + k4.w) * w4.w;
            }
            float s = (s0 + s1) + (s2 + s3);
            es[buf][i][lane] = valid ? __expf(s * mult) : 0.f;
        }
        if (c > 0) {
            int pbuf = buf ^ 1;
            #pragma unroll
            for (int j = 0; j < 32; j++) {
                float e = es[pbuf][i2][j];
                float4 v = *(const float4*)&vs[pbuf][j][g*4];
                acc.x += e*v.x; acc.y += e*v.y; acc.z += e*v.z; acc.w += e*v.w;
                denom += e;
            }
        }
        __syncthreads();
    }
    {
        int pbuf = (nchunk - 1) & 1;
        #pragma unroll
        for (int j = 0; j < 32; j++) {
            float e = es[pbuf][i2][j];
            float4 v = *(const float4*)&vs[pbuf][j][g*4];
            acc.x += e*v.x; acc.y += e*v.y; acc.z += e*v.z; acc.w += e*v.w;
            denom += e;
        }
    }

    float inv = 1.f / denom;
    float vals[4] = {acc.x*inv, acc.y*inv, acc.z*inv, acc.w*inv};
    int base = (b*LQ + ib*16 + i2) * DM + h*DK + g*4;
    #pragma unroll
    for (int u = 0; u < 4; u++) {
        __nv_bfloat16 hh = __float2bfloat16(vals[u]);
        g_Xhi[base + u] = hh;
        g_Xlo[base + u] = __float2bfloat16(vals[u] - __bfloat162float(hh));
    }
}

// ---------------------------------------------------------------------------
extern "C" void kernel_launch(void* const* d_in, const int* in_sizes, int n_in,
                              void* d_out, int out_size)
{
    const float* query = (const float*)d_in[0];
    const float* key_  = (const float*)d_in[1];
    const float* value = (const float*)d_in[2];
    const int*   mask  = (const int*)  d_in[3];
    const float* Wq    = (const float*)d_in[4];
    const float* Wk    = (const float*)d_in[5];
    const float* Wv    = (const float*)d_in[6];
    const float* Wo    = (const float*)d_in[7];
    const float* wa    = (const float*)d_in[8];
    float* out = (float*)d_out;

    convert_kernel<<<2304, 256>>>(query, key_, value, Wq, Wk, Wv, Wo);
    proj_kernel<<<dim3(8, 16, 3), 256>>>(mask);
    attn_kernel<<<256, 256>>>(wa);
    out_gemm<<<dim3(8, 16), 256>>>(out);
}